// round 12
// baseline (speedup 1.0000x reference)
#include <cuda_runtime.h>
#include <cuda_fp16.h>
#include <stdint.h>
#include <math.h>

// DCGRU cell. N=4096, B=32, IN_DIM=2, U=64, K=2, 2 supports -> M=5, F=66, C=F*B=2112.
// Supports ~1% sparse -> on-device nnz-sorted SELL-32 + smem-tiled SpMM (fp16 tiles,
// fp32 accumulation, 16-col tiles / 132 CTAs). Chebyshev folded into weights.
// GEMMs: three uniform OUT=64 SIMT f32x2 launches with fused GRU epilogues; the
// u-gate GEMM runs on a side stream overlapped with gconv2's SpMM (critical path).

#define NV 4096
#define BV 32
#define FV 66
#define CV (FV*BV)        // 2112
#define UV 64
#define NG 128            // row groups of 32
#define SELL_CAP 420000
#define TW 16             // SpMM column-tile width
#define NT (CV/TW)        // 132 tiles -> single wave on 148 SMs
#define RSTRIDE 3         // tile row stride in 16B units (48 B; gcd(3,8)=1 bank spread)

typedef unsigned long long ull;

// ---------------- device scratch ----------------
__device__ __align__(16) __half g_X1[(size_t)NV*CV];  // x0 for gconv1
__device__ __align__(16) __half g_X2[(size_t)NV*CV];  // x0 for gconv2 (inputs + r*hx)
__device__ __align__(16) __half g_M1[(size_t)NV*CV];  // S0 @ x0
__device__ __align__(16) __half g_M2[(size_t)NV*CV];  // S0 @ M1 (Chebyshev in weights)
__device__ __align__(16) __half g_M3[(size_t)NV*CV];  // S1 @ x0
__device__ __align__(16) __half g_M4[(size_t)NV*CV];  // S1 @ M3
__device__ float g_U [(size_t)BV*NV*UV];              // u gate (fp32), [b][n][o]
__device__ float g_W1p[330*128];
__device__ float g_W2p[330*64];
__device__ int   g_cnt[2][NV];
__device__ int   g_rows[2][NV];
__device__ int   g_slot[2][NV];
__device__ int   g_gw [2][NG];
__device__ int   g_goff[2][NG+1];
__device__ ull   g_ent[2][SELL_CAP];     // SELL: {val:hi32, col:lo32} at goff + j*32 + lane

// ---------------- per-row nnz count (grid (NV,2), block 256) ----------------
__global__ void k_count(const float* __restrict__ S0, const float* __restrict__ S1) {
    int row = blockIdx.x, s = blockIdx.y, t = threadIdx.x;
    const float4* S = (const float4*)((s ? S1 : S0) + (size_t)row * NV) + t * 4;
    int cnt = 0;
    #pragma unroll
    for (int j = 0; j < 4; j++) {
        float4 v = S[j];
        cnt += (v.x != 0.0f) + (v.y != 0.0f) + (v.z != 0.0f) + (v.w != 0.0f);
    }
    __shared__ int sm[256];
    sm[t] = cnt; __syncthreads();
    for (int o = 128; o > 0; o >>= 1) { if (t < o) sm[t] += sm[t + o]; __syncthreads(); }
    if (t == 0) g_cnt[s][row] = sm[0];
}

// ---------------- fillX + weight fold (side stream; independent of CSR) ----------
// y = (W0-W2-W4) x0 + W1 M1 + 2W2 M2' + W3 M3 + 2W4 M4'
#define NB_FILLX ((NV*CV)/256)           // 33792
#define NB_WPREP (((330*128+330*64)+255)/256) // 248
__global__ void k_fxw(const float* __restrict__ inp, const float* __restrict__ hx,
                      const float* __restrict__ W1, const float* __restrict__ W2) {
    int blk = blockIdx.x, t = threadIdx.x;
    if (blk < NB_FILLX) {
        int idx = blk * 256 + t;
        int n = idx / CV, col = idx - n * CV;
        int f = col >> 5, b = col & 31;
        float val;
        if (f < 2) { val = inp[(size_t)b * (NV * 2) + n * 2 + f]; g_X2[idx] = __float2half(val); }
        else         val = hx[(size_t)b * (NV * UV) + n * UV + (f - 2)];
        g_X1[idx] = __float2half(val);
    } else {
        int idx = (blk - NB_FILLX) * 256 + t;
        if (idx < 330 * 128) {
            int k = idx >> 7, m = k % 5;
            float v;
            if (m == 0)      v = W1[idx] - W1[idx + 2*128] - W1[idx + 4*128];
            else if (m == 2 || m == 4) v = 2.0f * W1[idx];
            else             v = W1[idx];
            g_W1p[idx] = v;
        } else if (idx < 330 * 128 + 330 * 64) {
            int j = idx - 330 * 128;
            int k = j >> 6, m = k % 5;
            float v;
            if (m == 0)      v = W2[j] - W2[j + 2*64] - W2[j + 4*64];
            else if (m == 2 || m == 4) v = 2.0f * W2[j];
            else             v = W2[j];
            g_W2p[j] = v;
        }
    }
}

// ---------------- counting sort rows by nnz, descending (grid 2, block 1024) -------
__global__ void k_sort() {
    int s = blockIdx.x, t = threadIdx.x;
    __shared__ int hist[256], suf[256], off[256];
    if (t < 256) { hist[t] = 0; off[t] = 0; }
    __syncthreads();
    int c[4];
    #pragma unroll
    for (int i = 0; i < 4; i++) {
        int r = t * 4 + i;
        c[i] = min(g_cnt[s][r], 255);
        atomicAdd(&hist[c[i]], 1);
    }
    __syncthreads();
    if (t < 256) suf[t] = hist[t];
    __syncthreads();
    for (int o = 1; o < 256; o <<= 1) {
        int v = 0;
        if (t < 256 && t + o < 256) v = suf[t + o];
        __syncthreads();
        if (t < 256) suf[t] += v;
        __syncthreads();
    }
    #pragma unroll
    for (int i = 0; i < 4; i++) {
        int r = t * 4 + i;
        int base = suf[c[i]] - hist[c[i]];
        int pos = base + atomicAdd(&off[c[i]], 1);
        g_rows[s][pos] = r;
        g_slot[s][r] = pos;
    }
}

// ---------------- group widths + offsets (grid 2, block 128) ----------------
__global__ void k_groups() {
    int s = blockIdx.x, g = threadIdx.x;
    int mx = 0;
    #pragma unroll 8
    for (int i = 0; i < 32; i++) mx = max(mx, g_cnt[s][g_rows[s][g * 32 + i]]);
    g_gw[s][g] = mx;
    __shared__ int sw[NG];
    int v = mx * 32;
    sw[g] = v; __syncthreads();
    for (int o = 1; o < NG; o <<= 1) {
        int y = (g >= o) ? sw[g - o] : 0;
        __syncthreads();
        sw[g] += y;
        __syncthreads();
    }
    g_goff[s][g] = sw[g] - v;
    if (g == NG - 1) g_goff[s][NG] = sw[g];
}

// ---------------- SELL fill (grid (4096,2), block 256) ----------------
__global__ void k_fill(const float* __restrict__ S0, const float* __restrict__ S1) {
    int row = blockIdx.x, s = blockIdx.y, t = threadIdx.x;
    const float* S = (s ? S1 : S0) + (size_t)row * NV;
    float4 va[4];
    #pragma unroll
    for (int j = 0; j < 4; j++) va[j] = ((const float4*)S)[t * 4 + j];
    const float* vf = (const float*)va;
    int cnt = 0;
    #pragma unroll
    for (int j = 0; j < 16; j++) cnt += (vf[j] != 0.0f);
    int lane = t & 31, w = t >> 5;
    int x = cnt;
    #pragma unroll
    for (int o = 1; o < 32; o <<= 1) { int y = __shfl_up_sync(~0u, x, o); if (lane >= o) x += y; }
    __shared__ int ws[8];
    if (lane == 31) ws[w] = x;
    __syncthreads();
    int woff = 0;
    for (int i = 0; i < w; i++) woff += ws[i];
    int slot = g_slot[s][row];
    int g = slot >> 5, sl = slot & 31;
    int base = g_goff[s][g] + sl;
    int width = g_gw[s][g];
    int rank = woff + x - cnt;
    #pragma unroll
    for (int j = 0; j < 16; j++) {
        float v = vf[j];
        if (v != 0.0f) {
            int dst = base + rank * 32;
            if (dst < SELL_CAP)
                g_ent[s][dst] = ((ull)(unsigned)__float_as_uint(v) << 32) | (unsigned)(t * 16 + j);
            rank++;
        }
    }
    int cr = g_cnt[s][row];
    for (int j = cr + t; j < width; j += 256) {
        int dst = base + j * 32;
        if (dst < SELL_CAP) g_ent[s][dst] = 0ull;
    }
}

// ---------------- SpMM core (unchanged from R11) ----------------
__device__ __forceinline__ void load_tile(uint4* tq, const __half* __restrict__ X,
                                          int c0, int t) {
    #pragma unroll
    for (int k = 0; k < 8; k++) {
        int i = t + (k << 10);
        int row = i >> 1, h = i & 1;
        tq[row * RSTRIDE + h] = *(const uint4*)(X + (size_t)row * CV + c0 + (h << 3));
    }
}

__device__ __forceinline__ void accum(ull e, const uint4* tq, float* a) {
    unsigned c = (unsigned)e;
    float v = __uint_as_float((unsigned)(e >> 32));
    const uint4* p = tq + c * RSTRIDE;
    uint4 q0 = p[0];
    uint4 q1 = p[1];
    float2 f;
    f = __half22float2(*reinterpret_cast<__half2*>(&q0.x)); a[0]  += v * f.x; a[1]  += v * f.y;
    f = __half22float2(*reinterpret_cast<__half2*>(&q0.y)); a[2]  += v * f.x; a[3]  += v * f.y;
    f = __half22float2(*reinterpret_cast<__half2*>(&q0.z)); a[4]  += v * f.x; a[5]  += v * f.y;
    f = __half22float2(*reinterpret_cast<__half2*>(&q0.w)); a[6]  += v * f.x; a[7]  += v * f.y;
    f = __half22float2(*reinterpret_cast<__half2*>(&q1.x)); a[8]  += v * f.x; a[9]  += v * f.y;
    f = __half22float2(*reinterpret_cast<__half2*>(&q1.y)); a[10] += v * f.x; a[11] += v * f.y;
    f = __half22float2(*reinterpret_cast<__half2*>(&q1.z)); a[12] += v * f.x; a[13] += v * f.y;
    f = __half22float2(*reinterpret_cast<__half2*>(&q1.w)); a[14] += v * f.x; a[15] += v * f.y;
}

__device__ __forceinline__ void sweep(const uint4* tq, const ull* __restrict__ ent,
                                      const int* __restrict__ goff, const int* __restrict__ gw,
                                      const int* __restrict__ rows,
                                      __half* __restrict__ Y, int c0, int t) {
    int lane = t & 31, w = t >> 5;
    #pragma unroll 1
    for (int g = w; g < NG; g += 32) {
        const ull* ep = ent + goff[g] + lane;
        int width = gw[g];
        float a[16];
        #pragma unroll
        for (int i = 0; i < 16; i++) a[i] = 0.0f;
        int j = 0;
        for (; j + 4 <= width; j += 4) {
            ull e0 = __ldg(ep + (j    ) * 32);
            ull e1 = __ldg(ep + (j + 1) * 32);
            ull e2 = __ldg(ep + (j + 2) * 32);
            ull e3 = __ldg(ep + (j + 3) * 32);
            accum(e0, tq, a); accum(e1, tq, a);
            accum(e2, tq, a); accum(e3, tq, a);
        }
        for (; j < width; j++) accum(__ldg(ep + j * 32), tq, a);
        int r = __ldg(rows + g * 32 + lane);
        uint4 o0, o1;
        __half2 h;
        h = __float22half2_rn(make_float2(a[0],  a[1]));  o0.x = *reinterpret_cast<unsigned*>(&h);
        h = __float22half2_rn(make_float2(a[2],  a[3]));  o0.y = *reinterpret_cast<unsigned*>(&h);
        h = __float22half2_rn(make_float2(a[4],  a[5]));  o0.z = *reinterpret_cast<unsigned*>(&h);
        h = __float22half2_rn(make_float2(a[6],  a[7]));  o0.w = *reinterpret_cast<unsigned*>(&h);
        h = __float22half2_rn(make_float2(a[8],  a[9]));  o1.x = *reinterpret_cast<unsigned*>(&h);
        h = __float22half2_rn(make_float2(a[10], a[11])); o1.y = *reinterpret_cast<unsigned*>(&h);
        h = __float22half2_rn(make_float2(a[12], a[13])); o1.z = *reinterpret_cast<unsigned*>(&h);
        h = __float22half2_rn(make_float2(a[14], a[15])); o1.w = *reinterpret_cast<unsigned*>(&h);
        uint4* op = (uint4*)(Y + (size_t)r * CV + c0);
        op[0] = o0; op[1] = o1;
    }
}

__global__ void __launch_bounds__(1024) k_spmmA(int which) {
    extern __shared__ uint4 tq[];
    int t = threadIdx.x, c0 = blockIdx.x * TW;
    load_tile(tq, which ? g_X2 : g_X1, c0, t);
    __syncthreads();
    sweep(tq, g_ent[0], g_goff[0], g_gw[0], g_rows[0], g_M1, c0, t);
    sweep(tq, g_ent[1], g_goff[1], g_gw[1], g_rows[1], g_M3, c0, t);
}

__global__ void __launch_bounds__(1024) k_spmmB() {
    extern __shared__ uint4 tq[];
    int t = threadIdx.x, c0 = blockIdx.x * TW;
    load_tile(tq, g_M1, c0, t);
    __syncthreads();
    sweep(tq, g_ent[0], g_goff[0], g_gw[0], g_rows[0], g_M2, c0, t);
    __syncthreads();
    load_tile(tq, g_M3, c0, t);
    __syncthreads();
    sweep(tq, g_ent[1], g_goff[1], g_gw[1], g_rows[1], g_M4, c0, t);
}

// ---------------- uniform OUT=64 GEMM: (B*N, 330) @ (330, 64), fused epilogues -----
// MODE 1: W1p cols 0..63,   sigmoid -> r*hx into g_X2 state slot.
// MODE 3: W1p cols 64..127, sigmoid -> u into g_U.
// MODE 2: W2p,              tanh    -> out = u*hx + (1-u)*c.
template<int MODE>
__global__ void __launch_bounds__(256, 2) k_gemm64(const float* __restrict__ bias,
                                                   const float* __restrict__ hx,
                                                   float* __restrict__ dout) {
    extern __shared__ float smem[];
    float* As = smem;                 // [66][128]
    float* Ws = smem + 66 * 128;      // [66][64]
    const float* __restrict__ W = (MODE == 2) ? g_W2p : g_W1p;
    constexpr int WS = (MODE == 2) ? 64 : 128;
    constexpr int WOFF = (MODE == 3) ? 64 : 0;
    const int t = threadIdx.x;
    const int n0 = blockIdx.x * 4;
    const int tr = t >> 3, tc = t & 7;   // 32 row-groups x 8 col-groups
    const int r0 = tr * 4, c0 = tc * 8;

    ull acc2[4][4];
    #pragma unroll
    for (int r = 0; r < 4; r++)
        #pragma unroll
        for (int j = 0; j < 4; j++) acc2[r][j] = 0ull;

    #pragma unroll 1
    for (int m = 0; m < 5; m++) {
        const __half* Mm = (m == 0) ? (MODE == 2 ? g_X2 : g_X1)
                         : (m == 1) ? g_M1 : (m == 2) ? g_M2
                         : (m == 3) ? g_M3 : g_M4;
        for (int i = t; i < 66 * 64; i += 256) {     // 4224 half2 pairs = 66x128 floats
            int b2 = i & 15, r2 = i >> 4;
            int f = r2 % 66, nl = r2 / 66;
            float2 fv = __half22float2(*(const __half2*)(Mm + (size_t)(n0 + nl) * CV + f * 32 + b2 * 2));
            As[f * 128 + nl * 32 + b2 * 2]     = fv.x;
            As[f * 128 + nl * 32 + b2 * 2 + 1] = fv.y;
        }
        for (int i = t; i < 66 * 64; i += 256) {
            int o = i & 63, f = i >> 6;
            Ws[f * 64 + o] = W[(f * 5 + m) * WS + WOFF + o];
        }
        __syncthreads();
        #pragma unroll 2
        for (int f = 0; f < 66; f++) {
            ull w2[4];
            const ull* wp = (const ull*)(Ws + f * 64 + c0);
            #pragma unroll
            for (int j = 0; j < 4; j++) w2[j] = wp[j];
            const float* ap = As + f * 128 + r0;
            #pragma unroll
            for (int r = 0; r < 4; r++) {
                float a = ap[r];
                ull a2;
                asm("mov.b64 %0, {%1, %1};" : "=l"(a2) : "r"(__float_as_uint(a)));
                #pragma unroll
                for (int j = 0; j < 4; j++)
                    asm("fma.rn.f32x2 %0, %1, %2, %0;" : "+l"(acc2[r][j]) : "l"(a2), "l"(w2[j]));
            }
        }
        __syncthreads();
    }

    #pragma unroll
    for (int r = 0; r < 4; r++) {
        int row = r0 + r, nl = row >> 5, b = row & 31, n = n0 + nl;
        #pragma unroll
        for (int j = 0; j < 4; j++) {
            unsigned lo, hi;
            asm("mov.b64 {%0, %1}, %2;" : "=r"(lo), "=r"(hi) : "l"(acc2[r][j]));
            float v[2] = { __uint_as_float(lo), __uint_as_float(hi) };
            #pragma unroll
            for (int q = 0; q < 2; q++) {
                int o = c0 + j * 2 + q;
                float x = v[q] + bias[o];
                if (MODE == 1) {
                    float sg = 1.0f / (1.0f + expf(-x));
                    float rh = sg * hx[(size_t)b * (NV * UV) + n * UV + o];
                    g_X2[(size_t)n * CV + (2 + o) * 32 + b] = __float2half(rh);
                } else if (MODE == 3) {
                    float sg = 1.0f / (1.0f + expf(-x));
                    g_U[((size_t)b * NV + n) * UV + o] = sg;
                } else {
                    float cv = tanhf(x);
                    float h = hx[(size_t)b * (NV * UV) + n * UV + o];
                    float u = g_U[((size_t)b * NV + n) * UV + o];
                    dout[(size_t)b * (NV * UV) + n * UV + o] = u * h + (1.0f - u) * cv;
                }
            }
        }
    }
}

// ---------------- launch ----------------
extern "C" void kernel_launch(void* const* d_in, const int* in_sizes, int n_in,
                              void* d_out, int out_size) {
    const float* inp = (const float*)d_in[0];
    const float* hx  = (const float*)d_in[1];
    const float* S0  = (const float*)d_in[2];
    const float* S1  = (const float*)d_in[3];
    const float* W1  = (const float*)d_in[4];
    const float* B1  = (const float*)d_in[5];
    const float* W2  = (const float*)d_in[6];
    const float* B2  = (const float*)d_in[7];
    float* out = (float*)d_out;

    // side stream + events, created once on the (non-captured) correctness call
    static cudaStream_t s2 = nullptr;
    static cudaEvent_t evA = nullptr, evB = nullptr, evC = nullptr, evD = nullptr;
    if (!s2) {
        cudaStreamCreateWithFlags(&s2, cudaStreamNonBlocking);
        cudaEventCreateWithFlags(&evA, cudaEventDisableTiming);
        cudaEventCreateWithFlags(&evB, cudaEventDisableTiming);
        cudaEventCreateWithFlags(&evC, cudaEventDisableTiming);
        cudaEventCreateWithFlags(&evD, cudaEventDisableTiming);
    }

    const size_t tile_smem = (size_t)NV * RSTRIDE * 16;              // 196608
    const size_t gemm_smem = (66 * 128 + 66 * 64) * sizeof(float);   // 50688
    cudaFuncSetAttribute(k_spmmA, cudaFuncAttributeMaxDynamicSharedMemorySize, (int)tile_smem);
    cudaFuncSetAttribute(k_spmmB, cudaFuncAttributeMaxDynamicSharedMemorySize, (int)tile_smem);
    cudaFuncSetAttribute(k_gemm64<1>, cudaFuncAttributeMaxDynamicSharedMemorySize, (int)gemm_smem);
    cudaFuncSetAttribute(k_gemm64<3>, cudaFuncAttributeMaxDynamicSharedMemorySize, (int)gemm_smem);
    cudaFuncSetAttribute(k_gemm64<2>, cudaFuncAttributeMaxDynamicSharedMemorySize, (int)gemm_smem);

    // CSR chain on main; fillX + weight fold overlapped on s2
    k_count<<<dim3(NV, 2), 256>>>(S0, S1);
    cudaEventRecord(evA, 0);
    cudaStreamWaitEvent(s2, evA, 0);
    k_fxw<<<NB_FILLX + NB_WPREP, 256, 0, s2>>>(inp, hx, W1, W2);
    cudaEventRecord(evB, s2);
    k_sort<<<2, 1024>>>();
    k_groups<<<2, NG>>>();
    k_fill<<<dim3(NV, 2), 256>>>(S0, S1);
    cudaStreamWaitEvent(0, evB, 0);          // X1/X2-inputs + folded W ready

    // gconv 1 (state = hx)
    k_spmmA<<<NT, 1024, tile_smem>>>(0);
    k_spmmB<<<NT, 1024, tile_smem>>>();
    cudaEventRecord(evC, 0);                 // M1..M4 + X1 ready
    cudaStreamWaitEvent(s2, evC, 0);
    k_gemm64<3><<<NV / 4, 256, gemm_smem, s2>>>(B1 + UV, hx, out);  // u-half, overlapped
    k_gemm64<1><<<NV / 4, 256, gemm_smem>>>(B1, hx, out);           // r-half, critical path

    // gconv 2 (state = r*hx, built by the r-half epilogue into g_X2)
    k_spmmA<<<NT, 1024, tile_smem>>>(1);
    k_spmmB<<<NT, 1024, tile_smem>>>();
    cudaEventRecord(evD, s2);
    cudaStreamWaitEvent(0, evD, 0);          // u gate ready
    k_gemm64<2><<<NV / 4, 256, gemm_smem>>>(B2, hx, out);
}

// round 15
// speedup vs baseline: 1.1319x; 1.1319x over previous
#include <cuda_runtime.h>
#include <cuda_fp16.h>
#include <stdint.h>
#include <math.h>

// DCGRU cell. N=4096, B=32, IN_DIM=2, U=64, K=2, 2 supports -> M=5, F=66, C=F*B=2112.
// Supports ~1% sparse -> on-device nnz-sorted SELL-32 + smem-tiled SpMM (fp16 tiles,
// fp32 accumulation, 16-col tiles / 132 CTAs = single wave). Chebyshev folded into
// weights. Dense GEMMs f32x2 SIMT FMA with fused sigmoid/tanh/GRU epilogues.
// Serial schedule (stream overlap regressed in R12: SM/smem contention).
// Prep chain: count pass also compacts entries (no second dense scan of S).

#define NV 4096
#define BV 32
#define FV 66
#define CV (FV*BV)        // 2112
#define UV 64
#define NG 128            // row groups of 32
#define SELL_CAP 420000
#define TW 16             // SpMM column-tile width
#define NT (CV/TW)        // 132 tiles -> single wave on 148 SMs
#define RSTRIDE 3         // tile row stride in 16B units (48 B; gcd(3,8)=1 bank spread)
#define TMP_W 112         // per-row compact entry capacity (P[nnz>112] ~ 1e-16)

typedef unsigned long long ull;

// ---------------- device scratch ----------------
__device__ __align__(16) __half g_X1[(size_t)NV*CV];  // x0 for gconv1
__device__ __align__(16) __half g_X2[(size_t)NV*CV];  // x0 for gconv2 (inputs + r*hx)
__device__ __align__(16) __half g_M1[(size_t)NV*CV];  // S0 @ x0
__device__ __align__(16) __half g_M2[(size_t)NV*CV];  // S0 @ M1 (Chebyshev in weights)
__device__ __align__(16) __half g_M3[(size_t)NV*CV];  // S1 @ x0
__device__ __align__(16) __half g_M4[(size_t)NV*CV];  // S1 @ M3
__device__ float g_U [(size_t)BV*NV*UV];              // u gate (fp32), [b][n][o]
__device__ float g_W1p[330*128];
__device__ float g_W2p[330*64];
__device__ int   g_cnt[2][NV];
__device__ int   g_rows[2][NV];
__device__ int   g_slot[2][NV];
__device__ int   g_gw [2][NG];
__device__ int   g_goff[2][NG+1];
__device__ ull   g_tmp[2][NV][TMP_W];    // compact per-row entries (column order)
__device__ ull   g_ent[2][SELL_CAP];     // SELL: {val:hi32, col:lo32} at goff + j*32 + lane

// ---------------- fused prep: fillX + count/compact + weight fold ----------------
// y = (W0-W2-W4) x0 + W1 M1 + 2W2 M2' + W3 M3 + 2W4 M4'
#define NB_FILLX ((NV*CV)/256)           // 33792
#define NB_COUNT (2*NV)                  // 8192
#define NB_WPREP (((330*128+330*64)+255)/256) // 248
__global__ void k_prep(const float* __restrict__ inp, const float* __restrict__ hx,
                       const float* __restrict__ S0, const float* __restrict__ S1,
                       const float* __restrict__ W1, const float* __restrict__ W2) {
    int blk = blockIdx.x, t = threadIdx.x;
    if (blk < NB_FILLX) {
        int idx = blk * 256 + t;
        int n = idx / CV, col = idx - n * CV;
        int f = col >> 5, b = col & 31;
        float val;
        if (f < 2) { val = inp[(size_t)b * (NV * 2) + n * 2 + f]; g_X2[idx] = __float2half(val); }
        else         val = hx[(size_t)b * (NV * UV) + n * UV + (f - 2)];
        g_X1[idx] = __float2half(val);
    } else if (blk < NB_FILLX + NB_COUNT) {
        // count + compact into g_tmp (column order preserved)
        int b2 = blk - NB_FILLX;
        int s = b2 >> 12, row = b2 & (NV - 1);
        const float* S = (s ? S1 : S0) + (size_t)row * NV;
        float4 va[4];
        #pragma unroll
        for (int j = 0; j < 4; j++) va[j] = ((const float4*)S)[t * 4 + j];
        const float* vf = (const float*)va;
        int cnt = 0;
        #pragma unroll
        for (int j = 0; j < 16; j++) cnt += (vf[j] != 0.0f);
        int lane = t & 31, w = t >> 5;
        int x = cnt;
        #pragma unroll
        for (int o = 1; o < 32; o <<= 1) { int y = __shfl_up_sync(~0u, x, o); if (lane >= o) x += y; }
        __shared__ int ws[8];
        if (lane == 31) ws[w] = x;
        __syncthreads();
        int woff = 0, total = 0;
        #pragma unroll
        for (int i = 0; i < 8; i++) { if (i < w) woff += ws[i]; total += ws[i]; }
        int rank = woff + x - cnt;
        ull* tp = g_tmp[s][row];
        #pragma unroll
        for (int j = 0; j < 16; j++) {
            float v = vf[j];
            if (v != 0.0f) {
                if (rank < TMP_W)
                    tp[rank] = ((ull)(unsigned)__float_as_uint(v) << 32) | (unsigned)(t * 16 + j);
                rank++;
            }
        }
        if (t == 0) g_cnt[s][row] = total;
    } else {
        int idx = (blk - NB_FILLX - NB_COUNT) * 256 + t;
        if (idx < 330 * 128) {
            int k = idx >> 7, m = k % 5;
            float v;
            if (m == 0)      v = W1[idx] - W1[idx + 2*128] - W1[idx + 4*128];
            else if (m == 2 || m == 4) v = 2.0f * W1[idx];
            else             v = W1[idx];
            g_W1p[idx] = v;
        } else if (idx < 330 * 128 + 330 * 64) {
            int j = idx - 330 * 128;
            int k = j >> 6, m = k % 5;
            float v;
            if (m == 0)      v = W2[j] - W2[j + 2*64] - W2[j + 4*64];
            else if (m == 2 || m == 4) v = 2.0f * W2[j];
            else             v = W2[j];
            g_W2p[j] = v;
        }
    }
}

// ---------------- sort rows by nnz (desc) + group widths/offsets (grid 2, 1024) ----
// Equal-nnz placement uses atomics (order nondeterministic) but per-row SpMM results
// are independent of slot position, so the final output is deterministic.
__global__ void k_sortg() {
    int s = blockIdx.x, t = threadIdx.x;
    __shared__ int hist[256], suf[256], off[256];
    __shared__ int sw[NG];
    if (t < 256) { hist[t] = 0; off[t] = 0; }
    __syncthreads();
    int c[4];
    #pragma unroll
    for (int i = 0; i < 4; i++) {
        int r = t * 4 + i;
        c[i] = min(g_cnt[s][r], 255);
        atomicAdd(&hist[c[i]], 1);
    }
    __syncthreads();
    if (t < 256) suf[t] = hist[t];
    __syncthreads();
    for (int o = 1; o < 256; o <<= 1) {          // inclusive suffix scan
        int v = 0;
        if (t < 256 && t + o < 256) v = suf[t + o];
        __syncthreads();
        if (t < 256) suf[t] += v;
        __syncthreads();
    }
    #pragma unroll
    for (int i = 0; i < 4; i++) {
        int r = t * 4 + i;
        int base = suf[c[i]] - hist[c[i]];
        int pos = base + atomicAdd(&off[c[i]], 1);
        g_rows[s][pos] = r;
        g_slot[s][r] = pos;
    }
    __syncthreads();                             // g_rows visible block-wide

    // group widths + exclusive offsets
    int width_v = 0;
    if (t < NG) {
        int mx = 0;
        #pragma unroll 8
        for (int i = 0; i < 32; i++) mx = max(mx, g_cnt[s][g_rows[s][t * 32 + i]]);
        g_gw[s][t] = mx;
        width_v = mx * 32;
        sw[t] = width_v;
    }
    __syncthreads();
    for (int o = 1; o < NG; o <<= 1) {
        int y = 0;
        if (t < NG && t >= o) y = sw[t - o];
        __syncthreads();
        if (t < NG) sw[t] += y;
        __syncthreads();
    }
    if (t < NG) g_goff[s][t] = sw[t] - width_v;
    if (t == NG - 1) g_goff[s][NG] = sw[t];
}

// ---------------- SELL fill from compact tmp (grid (NV,2), block 128) ----------
__global__ void k_fillc() {
    int row = blockIdx.x, s = blockIdx.y, t = threadIdx.x;
    int slot = g_slot[s][row];
    int g = slot >> 5, sl = slot & 31;
    int base = g_goff[s][g] + sl;
    int width = g_gw[s][g];
    int cnt = g_cnt[s][row];
    const ull* tp = g_tmp[s][row];
    for (int j = t; j < width; j += 128) {
        ull e = (j < cnt && j < TMP_W) ? tp[j] : 0ull;
        int dst = base + j * 32;
        if (dst < SELL_CAP) g_ent[s][dst] = e;
    }
}

// ---------------- SpMM core (unchanged from R11) ----------------
__device__ __forceinline__ void load_tile(uint4* tq, const __half* __restrict__ X,
                                          int c0, int t) {
    #pragma unroll
    for (int k = 0; k < 8; k++) {
        int i = t + (k << 10);
        int row = i >> 1, h = i & 1;
        tq[row * RSTRIDE + h] = *(const uint4*)(X + (size_t)row * CV + c0 + (h << 3));
    }
}

__device__ __forceinline__ void accum(ull e, const uint4* tq, float* a) {
    unsigned c = (unsigned)e;
    float v = __uint_as_float((unsigned)(e >> 32));
    const uint4* p = tq + c * RSTRIDE;
    uint4 q0 = p[0];
    uint4 q1 = p[1];
    float2 f;
    f = __half22float2(*reinterpret_cast<__half2*>(&q0.x)); a[0]  += v * f.x; a[1]  += v * f.y;
    f = __half22float2(*reinterpret_cast<__half2*>(&q0.y)); a[2]  += v * f.x; a[3]  += v * f.y;
    f = __half22float2(*reinterpret_cast<__half2*>(&q0.z)); a[4]  += v * f.x; a[5]  += v * f.y;
    f = __half22float2(*reinterpret_cast<__half2*>(&q0.w)); a[6]  += v * f.x; a[7]  += v * f.y;
    f = __half22float2(*reinterpret_cast<__half2*>(&q1.x)); a[8]  += v * f.x; a[9]  += v * f.y;
    f = __half22float2(*reinterpret_cast<__half2*>(&q1.y)); a[10] += v * f.x; a[11] += v * f.y;
    f = __half22float2(*reinterpret_cast<__half2*>(&q1.z)); a[12] += v * f.x; a[13] += v * f.y;
    f = __half22float2(*reinterpret_cast<__half2*>(&q1.w)); a[14] += v * f.x; a[15] += v * f.y;
}

__device__ __forceinline__ void sweep(const uint4* tq, const ull* __restrict__ ent,
                                      const int* __restrict__ goff, const int* __restrict__ gw,
                                      const int* __restrict__ rows,
                                      __half* __restrict__ Y, int c0, int t) {
    int lane = t & 31, w = t >> 5;
    #pragma unroll 1
    for (int g = w; g < NG; g += 32) {
        const ull* ep = ent + goff[g] + lane;
        int width = gw[g];
        float a[16];
        #pragma unroll
        for (int i = 0; i < 16; i++) a[i] = 0.0f;
        int j = 0;
        for (; j + 4 <= width; j += 4) {
            ull e0 = __ldg(ep + (j    ) * 32);
            ull e1 = __ldg(ep + (j + 1) * 32);
            ull e2 = __ldg(ep + (j + 2) * 32);
            ull e3 = __ldg(ep + (j + 3) * 32);
            accum(e0, tq, a); accum(e1, tq, a);
            accum(e2, tq, a); accum(e3, tq, a);
        }
        for (; j < width; j++) accum(__ldg(ep + j * 32), tq, a);
        int r = __ldg(rows + g * 32 + lane);
        uint4 o0, o1;
        __half2 h;
        h = __float22half2_rn(make_float2(a[0],  a[1]));  o0.x = *reinterpret_cast<unsigned*>(&h);
        h = __float22half2_rn(make_float2(a[2],  a[3]));  o0.y = *reinterpret_cast<unsigned*>(&h);
        h = __float22half2_rn(make_float2(a[4],  a[5]));  o0.z = *reinterpret_cast<unsigned*>(&h);
        h = __float22half2_rn(make_float2(a[6],  a[7]));  o0.w = *reinterpret_cast<unsigned*>(&h);
        h = __float22half2_rn(make_float2(a[8],  a[9]));  o1.x = *reinterpret_cast<unsigned*>(&h);
        h = __float22half2_rn(make_float2(a[10], a[11])); o1.y = *reinterpret_cast<unsigned*>(&h);
        h = __float22half2_rn(make_float2(a[12], a[13])); o1.z = *reinterpret_cast<unsigned*>(&h);
        h = __float22half2_rn(make_float2(a[14], a[15])); o1.w = *reinterpret_cast<unsigned*>(&h);
        uint4* op = (uint4*)(Y + (size_t)r * CV + c0);
        op[0] = o0; op[1] = o1;
    }
}

__global__ void __launch_bounds__(1024) k_spmmA(int which) {
    extern __shared__ uint4 tq[];
    int t = threadIdx.x, c0 = blockIdx.x * TW;
    load_tile(tq, which ? g_X2 : g_X1, c0, t);
    __syncthreads();
    sweep(tq, g_ent[0], g_goff[0], g_gw[0], g_rows[0], g_M1, c0, t);
    sweep(tq, g_ent[1], g_goff[1], g_gw[1], g_rows[1], g_M3, c0, t);
}

__global__ void __launch_bounds__(1024) k_spmmB() {
    extern __shared__ uint4 tq[];
    int t = threadIdx.x, c0 = blockIdx.x * TW;
    load_tile(tq, g_M1, c0, t);
    __syncthreads();
    sweep(tq, g_ent[0], g_goff[0], g_gw[0], g_rows[0], g_M2, c0, t);
    __syncthreads();
    load_tile(tq, g_M3, c0, t);
    __syncthreads();
    sweep(tq, g_ent[1], g_goff[1], g_gw[1], g_rows[1], g_M4, c0, t);
}

// ---------------- dense GEMM: (B*N, 330) @ (330, OUT), fused epilogues ----------------
// MODE 1: sigmoid; cols<64 -> r*hx (fp16) into g_X2 state slot; cols>=64 -> g_U.
// MODE 2: tanh; out = u*hx + (1-u)*c.
template<int OUT, int MODE>
__global__ void __launch_bounds__(256, 2) k_gemm(const float* __restrict__ bias,
                                                 const float* __restrict__ hx,
                                                 float* __restrict__ dout) {
    extern __shared__ float smem[];
    float* As = smem;                 // [66][128]
    float* Ws = smem + 66 * 128;      // [66][OUT]
    const float* __restrict__ W = (MODE == 1) ? g_W1p : g_W2p;
    const int t = threadIdx.x;
    const int n0 = blockIdx.x * 4;
    constexpr int CT = OUT / 8;
    constexpr int MR = OUT / 16;
    const int tr = t / CT, tc = t % CT;
    const int r0 = tr * MR, c0 = tc * 8;

    ull acc2[MR][4];
    #pragma unroll
    for (int r = 0; r < MR; r++)
        #pragma unroll
        for (int j = 0; j < 4; j++) acc2[r][j] = 0ull;

    #pragma unroll 1
    for (int m = 0; m < 5; m++) {
        const __half* Mm = (m == 0) ? (MODE == 1 ? g_X1 : g_X2)
                         : (m == 1) ? g_M1 : (m == 2) ? g_M2
                         : (m == 3) ? g_M3 : g_M4;
        for (int i = t; i < 66 * 64; i += 256) {     // 4224 half2 pairs = 66x128 floats
            int b2 = i & 15, r2 = i >> 4;
            int f = r2 % 66, nl = r2 / 66;
            float2 fv = __half22float2(*(const __half2*)(Mm + (size_t)(n0 + nl) * CV + f * 32 + b2 * 2));
            As[f * 128 + nl * 32 + b2 * 2]     = fv.x;
            As[f * 128 + nl * 32 + b2 * 2 + 1] = fv.y;
        }
        for (int i = t; i < 66 * OUT; i += 256) {
            int o = i % OUT, f = i / OUT;
            Ws[f * OUT + o] = W[(f * 5 + m) * OUT + o];
        }
        __syncthreads();
        #pragma unroll 2
        for (int f = 0; f < 66; f++) {
            ull w2[4];
            const ull* wp = (const ull*)(Ws + f * OUT + c0);
            #pragma unroll
            for (int j = 0; j < 4; j++) w2[j] = wp[j];
            const float* ap = As + f * 128 + r0;
            #pragma unroll
            for (int r = 0; r < MR; r++) {
                float a = ap[r];
                ull a2;
                asm("mov.b64 %0, {%1, %1};" : "=l"(a2) : "r"(__float_as_uint(a)));
                #pragma unroll
                for (int j = 0; j < 4; j++)
                    asm("fma.rn.f32x2 %0, %1, %2, %0;" : "+l"(acc2[r][j]) : "l"(a2), "l"(w2[j]));
            }
        }
        __syncthreads();
    }

    #pragma unroll
    for (int r = 0; r < MR; r++) {
        int row = r0 + r, nl = row >> 5, b = row & 31, n = n0 + nl;
        #pragma unroll
        for (int j = 0; j < 4; j++) {
            unsigned lo, hi;
            asm("mov.b64 {%0, %1}, %2;" : "=r"(lo), "=r"(hi) : "l"(acc2[r][j]));
            float v[2] = { __uint_as_float(lo), __uint_as_float(hi) };
            #pragma unroll
            for (int q = 0; q < 2; q++) {
                int o = c0 + j * 2 + q;
                float x = v[q] + bias[o];
                if (MODE == 1) {
                    float sg = 1.0f / (1.0f + expf(-x));
                    if (o < UV) {
                        float rh = sg * hx[(size_t)b * (NV * UV) + n * UV + o];
                        g_X2[(size_t)n * CV + (2 + o) * 32 + b] = __float2half(rh);
                    } else {
                        g_U[((size_t)b * NV + n) * UV + (o - UV)] = sg;
                    }
                } else {
                    float cv = tanhf(x);
                    float h = hx[(size_t)b * (NV * UV) + n * UV + o];
                    float u = g_U[((size_t)b * NV + n) * UV + o];
                    dout[(size_t)b * (NV * UV) + n * UV + o] = u * h + (1.0f - u) * cv;
                }
            }
        }
    }
}

// ---------------- launch (serial; overlap regressed in R12) ----------------
extern "C" void kernel_launch(void* const* d_in, const int* in_sizes, int n_in,
                              void* d_out, int out_size) {
    const float* inp = (const float*)d_in[0];
    const float* hx  = (const float*)d_in[1];
    const float* S0  = (const float*)d_in[2];
    const float* S1  = (const float*)d_in[3];
    const float* W1  = (const float*)d_in[4];
    const float* B1  = (const float*)d_in[5];
    const float* W2  = (const float*)d_in[6];
    const float* B2  = (const float*)d_in[7];
    float* out = (float*)d_out;

    const size_t tile_smem = (size_t)NV * RSTRIDE * 16;              // 196608
    const size_t gemm1_smem = (66 * 128 + 66 * 128) * sizeof(float); // 67584
    const size_t gemm2_smem = (66 * 128 + 66 * 64) * sizeof(float);  // 50688
    cudaFuncSetAttribute(k_spmmA, cudaFuncAttributeMaxDynamicSharedMemorySize, (int)tile_smem);
    cudaFuncSetAttribute(k_spmmB, cudaFuncAttributeMaxDynamicSharedMemorySize, (int)tile_smem);
    cudaFuncSetAttribute(k_gemm<128,1>, cudaFuncAttributeMaxDynamicSharedMemorySize, (int)gemm1_smem);
    cudaFuncSetAttribute(k_gemm<64,2>,  cudaFuncAttributeMaxDynamicSharedMemorySize, (int)gemm2_smem);

    k_prep<<<NB_FILLX + NB_COUNT + NB_WPREP, 256>>>(inp, hx, S0, S1, W1, W2);
    k_sortg<<<2, 1024>>>();
    k_fillc<<<dim3(NV, 2), 128>>>();

    // gconv 1 (state = hx)
    k_spmmA<<<NT, 1024, tile_smem>>>(0);
    k_spmmB<<<NT, 1024, tile_smem>>>();
    k_gemm<128,1><<<NV / 4, 256, gemm1_smem>>>(B1, hx, out);

    // gconv 2 (state = r*hx, built by GEMM1 epilogue into g_X2)
    k_spmmA<<<NT, 1024, tile_smem>>>(1);
    k_spmmB<<<NT, 1024, tile_smem>>>();
    k_gemm<64,2><<<NV / 4, 256, gemm2_smem>>>(B2, hx, out);
}

// round 16
// speedup vs baseline: 1.1641x; 1.0284x over previous
#include <cuda_runtime.h>
#include <cuda_fp16.h>
#include <stdint.h>
#include <math.h>

// DCGRU cell. N=4096, B=32, IN_DIM=2, U=64, K=2, 2 supports -> M=5, F=66, C=F*B=2112.
// Supports ~1% sparse -> on-device nnz-sorted SELL-32 + smem-tiled SpMM (fp16 tiles,
// fp32 accumulation, 16-col tiles / 132 CTAs = single wave; all 4 support passes of a
// gconv fused in one kernel — each CTA's 2nd-hop tile is the stripe it wrote itself).
// Chebyshev folded into weights. Dense GEMMs f32x2 SIMT FMA with fused GRU epilogues.
// Serial schedule (stream overlap regressed in R12: SM/smem contention).

#define NV 4096
#define BV 32
#define FV 66
#define CV (FV*BV)        // 2112
#define UV 64
#define NG 128            // row groups of 32
#define SELL_CAP 420000
#define TW 16             // SpMM column-tile width
#define NT (CV/TW)        // 132 tiles -> single wave on 148 SMs
#define RSTRIDE 3         // tile row stride in 16B units (48 B; gcd(3,8)=1 bank spread)
#define TMP_W 112         // per-row compact entry capacity (P[nnz>112] ~ 1e-16)

typedef unsigned long long ull;

// ---------------- device scratch ----------------
__device__ __align__(16) __half g_X1[(size_t)NV*CV];  // x0 for gconv1
__device__ __align__(16) __half g_X2[(size_t)NV*CV];  // x0 for gconv2 (inputs + r*hx)
__device__ __align__(16) __half g_M1[(size_t)NV*CV];  // S0 @ x0
__device__ __align__(16) __half g_M2[(size_t)NV*CV];  // S0 @ M1 (Chebyshev in weights)
__device__ __align__(16) __half g_M3[(size_t)NV*CV];  // S1 @ x0
__device__ __align__(16) __half g_M4[(size_t)NV*CV];  // S1 @ M3
__device__ float g_U [(size_t)BV*NV*UV];              // u gate (fp32), [b][n][o]
__device__ float g_W1p[330*128];
__device__ float g_W2p[330*64];
__device__ int   g_cnt[2][NV];
__device__ int   g_rows[2][NV];
__device__ int   g_slot[2][NV];
__device__ int   g_gw [2][NG];
__device__ int   g_goff[2][NG+1];
__device__ ull   g_tmp[2][NV][TMP_W];    // compact per-row entries (column order)
__device__ ull   g_ent[2][SELL_CAP];     // SELL: {val:hi32, col:lo32} at goff + j*32 + lane

// ---------------- fused prep: fillX (coalesced transpose) + count/compact + W fold --
// y = (W0-W2-W4) x0 + W1 M1 + 2W2 M2' + W3 M3 + 2W4 M4'
#define NB_FILLX NV                      // one node per block (smem transpose)
#define NB_COUNT (2*NV)                  // 8192
#define NB_WPREP (((330*128+330*64)+255)/256) // 248
__global__ void k_prep(const float* __restrict__ inp, const float* __restrict__ hx,
                       const float* __restrict__ S0, const float* __restrict__ S1,
                       const float* __restrict__ W1, const float* __restrict__ W2) {
    int blk = blockIdx.x, t = threadIdx.x;
    if (blk < NB_FILLX) {
        // fillX for node n: stage hx[b][o] coalesced, emit X1 (and X2 inputs) coalesced
        int n = blk;
        __shared__ float sx[32][65];
        #pragma unroll
        for (int bi = 0; bi < 8; bi++) {
            int b = bi * 4 + (t >> 6), o = t & 63;
            sx[b][o] = hx[(size_t)b * (NV * UV) + n * UV + o];
        }
        __syncthreads();
        for (int col = t; col < CV; col += 256) {
            int f = col >> 5, b = col & 31;
            float val;
            if (f < 2) {
                val = inp[(size_t)b * (NV * 2) + n * 2 + f];
                g_X2[(size_t)n * CV + col] = __float2half(val);
            } else {
                val = sx[b][f - 2];
            }
            g_X1[(size_t)n * CV + col] = __float2half(val);
        }
    } else if (blk < NB_FILLX + NB_COUNT) {
        // count + compact into g_tmp (column order preserved)
        int b2 = blk - NB_FILLX;
        int s = b2 >> 12, row = b2 & (NV - 1);
        const float* S = (s ? S1 : S0) + (size_t)row * NV;
        float4 va[4];
        #pragma unroll
        for (int j = 0; j < 4; j++) va[j] = ((const float4*)S)[t * 4 + j];
        const float* vf = (const float*)va;
        int cnt = 0;
        #pragma unroll
        for (int j = 0; j < 16; j++) cnt += (vf[j] != 0.0f);
        int lane = t & 31, w = t >> 5;
        int x = cnt;
        #pragma unroll
        for (int o = 1; o < 32; o <<= 1) { int y = __shfl_up_sync(~0u, x, o); if (lane >= o) x += y; }
        __shared__ int ws[8];
        if (lane == 31) ws[w] = x;
        __syncthreads();
        int woff = 0, total = 0;
        #pragma unroll
        for (int i = 0; i < 8; i++) { if (i < w) woff += ws[i]; total += ws[i]; }
        int rank = woff + x - cnt;
        ull* tp = g_tmp[s][row];
        #pragma unroll
        for (int j = 0; j < 16; j++) {
            float v = vf[j];
            if (v != 0.0f) {
                if (rank < TMP_W)
                    tp[rank] = ((ull)(unsigned)__float_as_uint(v) << 32) | (unsigned)(t * 16 + j);
                rank++;
            }
        }
        if (t == 0) g_cnt[s][row] = total;
    } else {
        int idx = (blk - NB_FILLX - NB_COUNT) * 256 + t;
        if (idx < 330 * 128) {
            int k = idx >> 7, m = k % 5;
            float v;
            if (m == 0)      v = W1[idx] - W1[idx + 2*128] - W1[idx + 4*128];
            else if (m == 2 || m == 4) v = 2.0f * W1[idx];
            else             v = W1[idx];
            g_W1p[idx] = v;
        } else if (idx < 330 * 128 + 330 * 64) {
            int j = idx - 330 * 128;
            int k = j >> 6, m = k % 5;
            float v;
            if (m == 0)      v = W2[j] - W2[j + 2*64] - W2[j + 4*64];
            else if (m == 2 || m == 4) v = 2.0f * W2[j];
            else             v = W2[j];
            g_W2p[j] = v;
        }
    }
}

// ---------------- sort rows by nnz (desc) + group widths/offsets (grid 2, 1024) ----
// Equal-nnz placement uses atomics (order nondeterministic) but per-row SpMM results
// are independent of slot position, so the final output is deterministic.
__global__ void k_sortg() {
    int s = blockIdx.x, t = threadIdx.x;
    __shared__ int hist[256], suf[256], off[256];
    __shared__ int sw[NG];
    if (t < 256) { hist[t] = 0; off[t] = 0; }
    __syncthreads();
    int c[4];
    #pragma unroll
    for (int i = 0; i < 4; i++) {
        int r = t * 4 + i;
        c[i] = min(g_cnt[s][r], 255);
        atomicAdd(&hist[c[i]], 1);
    }
    __syncthreads();
    if (t < 256) suf[t] = hist[t];
    __syncthreads();
    for (int o = 1; o < 256; o <<= 1) {          // inclusive suffix scan
        int v = 0;
        if (t < 256 && t + o < 256) v = suf[t + o];
        __syncthreads();
        if (t < 256) suf[t] += v;
        __syncthreads();
    }
    #pragma unroll
    for (int i = 0; i < 4; i++) {
        int r = t * 4 + i;
        int base = suf[c[i]] - hist[c[i]];
        int pos = base + atomicAdd(&off[c[i]], 1);
        g_rows[s][pos] = r;
        g_slot[s][r] = pos;
    }
    __syncthreads();                             // g_rows visible block-wide

    int width_v = 0;
    if (t < NG) {
        int mx = 0;
        #pragma unroll 8
        for (int i = 0; i < 32; i++) mx = max(mx, g_cnt[s][g_rows[s][t * 32 + i]]);
        g_gw[s][t] = mx;
        width_v = mx * 32;
        sw[t] = width_v;
    }
    __syncthreads();
    for (int o = 1; o < NG; o <<= 1) {
        int y = 0;
        if (t < NG && t >= o) y = sw[t - o];
        __syncthreads();
        if (t < NG) sw[t] += y;
        __syncthreads();
    }
    if (t < NG) g_goff[s][t] = sw[t] - width_v;
    if (t == NG - 1) g_goff[s][NG] = sw[t];
}

// ---------------- SELL fill from compact tmp (grid (NV,2), block 128) ----------
__global__ void k_fillc() {
    int row = blockIdx.x, s = blockIdx.y, t = threadIdx.x;
    int slot = g_slot[s][row];
    int g = slot >> 5, sl = slot & 31;
    int base = g_goff[s][g] + sl;
    int width = g_gw[s][g];
    int cnt = g_cnt[s][row];
    const ull* tp = g_tmp[s][row];
    for (int j = t; j < width; j += 128) {
        ull e = (j < cnt && j < TMP_W) ? tp[j] : 0ull;
        int dst = base + j * 32;
        if (dst < SELL_CAP) g_ent[s][dst] = e;
    }
}

// ---------------- SpMM core ----------------
__device__ __forceinline__ void load_tile(uint4* tq, const __half* __restrict__ X,
                                          int c0, int t) {
    #pragma unroll
    for (int k = 0; k < 8; k++) {
        int i = t + (k << 10);
        int row = i >> 1, h = i & 1;
        tq[row * RSTRIDE + h] = *(const uint4*)(X + (size_t)row * CV + c0 + (h << 3));
    }
}

__device__ __forceinline__ void accum(ull e, const uint4* tq, float* a) {
    unsigned c = (unsigned)e;
    float v = __uint_as_float((unsigned)(e >> 32));
    const uint4* p = tq + c * RSTRIDE;
    uint4 q0 = p[0];
    uint4 q1 = p[1];
    float2 f;
    f = __half22float2(*reinterpret_cast<__half2*>(&q0.x)); a[0]  += v * f.x; a[1]  += v * f.y;
    f = __half22float2(*reinterpret_cast<__half2*>(&q0.y)); a[2]  += v * f.x; a[3]  += v * f.y;
    f = __half22float2(*reinterpret_cast<__half2*>(&q0.z)); a[4]  += v * f.x; a[5]  += v * f.y;
    f = __half22float2(*reinterpret_cast<__half2*>(&q0.w)); a[6]  += v * f.x; a[7]  += v * f.y;
    f = __half22float2(*reinterpret_cast<__half2*>(&q1.x)); a[8]  += v * f.x; a[9]  += v * f.y;
    f = __half22float2(*reinterpret_cast<__half2*>(&q1.y)); a[10] += v * f.x; a[11] += v * f.y;
    f = __half22float2(*reinterpret_cast<__half2*>(&q1.z)); a[12] += v * f.x; a[13] += v * f.y;
    f = __half22float2(*reinterpret_cast<__half2*>(&q1.w)); a[14] += v * f.x; a[15] += v * f.y;
}

__device__ __forceinline__ void sweep(const uint4* tq, const ull* __restrict__ ent,
                                      const int* __restrict__ goff, const int* __restrict__ gw,
                                      const int* __restrict__ rows,
                                      __half* __restrict__ Y, int c0, int t) {
    int lane = t & 31, w = t >> 5;
    #pragma unroll 1
    for (int g = w; g < NG; g += 32) {
        const ull* ep = ent + goff[g] + lane;
        int width = gw[g];
        float a[16];
        #pragma unroll
        for (int i = 0; i < 16; i++) a[i] = 0.0f;
        int j = 0;
        for (; j + 4 <= width; j += 4) {
            ull e0 = __ldg(ep + (j    ) * 32);
            ull e1 = __ldg(ep + (j + 1) * 32);
            ull e2 = __ldg(ep + (j + 2) * 32);
            ull e3 = __ldg(ep + (j + 3) * 32);
            accum(e0, tq, a); accum(e1, tq, a);
            accum(e2, tq, a); accum(e3, tq, a);
        }
        for (; j < width; j++) accum(__ldg(ep + j * 32), tq, a);
        int r = __ldg(rows + g * 32 + lane);
        uint4 o0, o1;
        __half2 h;
        h = __float22half2_rn(make_float2(a[0],  a[1]));  o0.x = *reinterpret_cast<unsigned*>(&h);
        h = __float22half2_rn(make_float2(a[2],  a[3]));  o0.y = *reinterpret_cast<unsigned*>(&h);
        h = __float22half2_rn(make_float2(a[4],  a[5]));  o0.z = *reinterpret_cast<unsigned*>(&h);
        h = __float22half2_rn(make_float2(a[6],  a[7]));  o0.w = *reinterpret_cast<unsigned*>(&h);
        h = __float22half2_rn(make_float2(a[8],  a[9]));  o1.x = *reinterpret_cast<unsigned*>(&h);
        h = __float22half2_rn(make_float2(a[10], a[11])); o1.y = *reinterpret_cast<unsigned*>(&h);
        h = __float22half2_rn(make_float2(a[12], a[13])); o1.z = *reinterpret_cast<unsigned*>(&h);
        h = __float22half2_rn(make_float2(a[14], a[15])); o1.w = *reinterpret_cast<unsigned*>(&h);
        uint4* op = (uint4*)(Y + (size_t)r * CV + c0);
        op[0] = o0; op[1] = o1;
    }
}

// Fused per-gconv SpMM: all 4 support passes in one kernel. A CTA's 2nd-hop tile
// (columns [c0, c0+16) of M1/M3, all rows) is exactly the stripe this CTA wrote in
// the 1st hop, so __syncthreads + reload from gmem (L2-hot, self-written) is sound.
__global__ void __launch_bounds__(1024) k_spmm(int which) {
    extern __shared__ uint4 tq[];
    int t = threadIdx.x, c0 = blockIdx.x * TW;
    load_tile(tq, which ? g_X2 : g_X1, c0, t);
    __syncthreads();
    sweep(tq, g_ent[0], g_goff[0], g_gw[0], g_rows[0], g_M1, c0, t);
    sweep(tq, g_ent[1], g_goff[1], g_gw[1], g_rows[1], g_M3, c0, t);
    __syncthreads();                 // all reads of X tile done; M1 stripe visible
    load_tile(tq, g_M1, c0, t);
    __syncthreads();
    sweep(tq, g_ent[0], g_goff[0], g_gw[0], g_rows[0], g_M2, c0, t);
    __syncthreads();                 // M3 stripe visible (written pre-barrier above)
    load_tile(tq, g_M3, c0, t);
    __syncthreads();
    sweep(tq, g_ent[1], g_goff[1], g_gw[1], g_rows[1], g_M4, c0, t);
}

// ---------------- dense GEMM: (B*N, 330) @ (330, OUT), fused epilogues ----------------
// MODE 1: sigmoid; cols<64 -> r*hx (fp16) into g_X2 state slot; cols>=64 -> g_U.
// MODE 2: tanh; out = u*hx + (1-u)*c.
template<int OUT, int MODE>
__global__ void __launch_bounds__(256, 2) k_gemm(const float* __restrict__ bias,
                                                 const float* __restrict__ hx,
                                                 float* __restrict__ dout) {
    extern __shared__ float smem[];
    float* As = smem;                 // [66][128]
    float* Ws = smem + 66 * 128;      // [66][OUT]
    const float* __restrict__ W = (MODE == 1) ? g_W1p : g_W2p;
    const int t = threadIdx.x;
    const int n0 = blockIdx.x * 4;
    constexpr int CT = OUT / 8;
    constexpr int MR = OUT / 16;
    const int tr = t / CT, tc = t % CT;
    const int r0 = tr * MR, c0 = tc * 8;

    ull acc2[MR][4];
    #pragma unroll
    for (int r = 0; r < MR; r++)
        #pragma unroll
        for (int j = 0; j < 4; j++) acc2[r][j] = 0ull;

    #pragma unroll 1
    for (int m = 0; m < 5; m++) {
        const __half* Mm = (m == 0) ? (MODE == 1 ? g_X1 : g_X2)
                         : (m == 1) ? g_M1 : (m == 2) ? g_M2
                         : (m == 3) ? g_M3 : g_M4;
        for (int i = t; i < 66 * 64; i += 256) {     // 4224 half2 pairs = 66x128 floats
            int b2 = i & 15, r2 = i >> 4;
            int f = r2 % 66, nl = r2 / 66;
            float2 fv = __half22float2(*(const __half2*)(Mm + (size_t)(n0 + nl) * CV + f * 32 + b2 * 2));
            As[f * 128 + nl * 32 + b2 * 2]     = fv.x;
            As[f * 128 + nl * 32 + b2 * 2 + 1] = fv.y;
        }
        for (int i = t; i < 66 * OUT; i += 256) {
            int o = i % OUT, f = i / OUT;
            Ws[f * OUT + o] = W[(f * 5 + m) * OUT + o];
        }
        __syncthreads();
        #pragma unroll 2
        for (int f = 0; f < 66; f++) {
            ull w2[4];
            const ull* wp = (const ull*)(Ws + f * OUT + c0);
            #pragma unroll
            for (int j = 0; j < 4; j++) w2[j] = wp[j];
            const float* ap = As + f * 128 + r0;
            #pragma unroll
            for (int r = 0; r < MR; r++) {
                float a = ap[r];
                ull a2;
                asm("mov.b64 %0, {%1, %1};" : "=l"(a2) : "r"(__float_as_uint(a)));
                #pragma unroll
                for (int j = 0; j < 4; j++)
                    asm("fma.rn.f32x2 %0, %1, %2, %0;" : "+l"(acc2[r][j]) : "l"(a2), "l"(w2[j]));
            }
        }
        __syncthreads();
    }

    #pragma unroll
    for (int r = 0; r < MR; r++) {
        int row = r0 + r, nl = row >> 5, b = row & 31, n = n0 + nl;
        #pragma unroll
        for (int j = 0; j < 4; j++) {
            unsigned lo, hi;
            asm("mov.b64 {%0, %1}, %2;" : "=r"(lo), "=r"(hi) : "l"(acc2[r][j]));
            float v[2] = { __uint_as_float(lo), __uint_as_float(hi) };
            #pragma unroll
            for (int q = 0; q < 2; q++) {
                int o = c0 + j * 2 + q;
                float x = v[q] + bias[o];
                if (MODE == 1) {
                    float sg = 1.0f / (1.0f + expf(-x));
                    if (o < UV) {
                        float rh = sg * hx[(size_t)b * (NV * UV) + n * UV + o];
                        g_X2[(size_t)n * CV + (2 + o) * 32 + b] = __float2half(rh);
                    } else {
                        g_U[((size_t)b * NV + n) * UV + (o - UV)] = sg;
                    }
                } else {
                    float cv = tanhf(x);
                    float h = hx[(size_t)b * (NV * UV) + n * UV + o];
                    float u = g_U[((size_t)b * NV + n) * UV + o];
                    dout[(size_t)b * (NV * UV) + n * UV + o] = u * h + (1.0f - u) * cv;
                }
            }
        }
    }
}

// ---------------- launch (serial; overlap regressed in R12) ----------------
extern "C" void kernel_launch(void* const* d_in, const int* in_sizes, int n_in,
                              void* d_out, int out_size) {
    const float* inp = (const float*)d_in[0];
    const float* hx  = (const float*)d_in[1];
    const float* S0  = (const float*)d_in[2];
    const float* S1  = (const float*)d_in[3];
    const float* W1  = (const float*)d_in[4];
    const float* B1  = (const float*)d_in[5];
    const float* W2  = (const float*)d_in[6];
    const float* B2  = (const float*)d_in[7];
    float* out = (float*)d_out;

    const size_t tile_smem = (size_t)NV * RSTRIDE * 16;              // 196608
    const size_t gemm1_smem = (66 * 128 + 66 * 128) * sizeof(float); // 67584
    const size_t gemm2_smem = (66 * 128 + 66 * 64) * sizeof(float);  // 50688
    cudaFuncSetAttribute(k_spmm, cudaFuncAttributeMaxDynamicSharedMemorySize, (int)tile_smem);
    cudaFuncSetAttribute(k_gemm<128,1>, cudaFuncAttributeMaxDynamicSharedMemorySize, (int)gemm1_smem);
    cudaFuncSetAttribute(k_gemm<64,2>,  cudaFuncAttributeMaxDynamicSharedMemorySize, (int)gemm2_smem);

    k_prep<<<NB_FILLX + NB_COUNT + NB_WPREP, 256>>>(inp, hx, S0, S1, W1, W2);
    k_sortg<<<2, 1024>>>();
    k_fillc<<<dim3(NV, 2), 128>>>();

    // gconv 1 (state = hx): all 4 support passes in one launch
    k_spmm<<<NT, 1024, tile_smem>>>(0);
    k_gemm<128,1><<<NV / 4, 256, gemm1_smem>>>(B1, hx, out);

    // gconv 2 (state = r*hx, built by GEMM1 epilogue into g_X2)
    k_spmm<<<NT, 1024, tile_smem>>>(1);
    k_gemm<64,2><<<NV / 4, 256, gemm2_smem>>>(B2, hx, out);
}